// round 17
// baseline (speedup 1.0000x reference)
#include <cuda_runtime.h>
#include <limits.h>

// Problem shape (fixed by setup_inputs): B=256, N=65536, half=32768.
#define NCOL   65536
#define HALF   32768
#define C8ROW  4096              // float8 per half-row
#define BDIM   512
#define NIT8   (C8ROW / BDIM)    // 8 iterations per half
#define MAXB   1024

#define THRESH  0.01f
#define PENALTY 2.0f

__device__ float        g_partials[MAXB];
__device__ unsigned int g_counter = 0;

struct f8 { float v[8]; };

// 256-bit loads with direct L2 evict hints (the sm_100-legal form).
__device__ __forceinline__ f8 ld8_keep(const float* p) {
    unsigned a0,a1,a2,a3,a4,a5,a6,a7;
    asm volatile("ld.global.nc.L2::evict_last.v8.b32 {%0,%1,%2,%3,%4,%5,%6,%7}, [%8];"
                 : "=r"(a0),"=r"(a1),"=r"(a2),"=r"(a3),
                   "=r"(a4),"=r"(a5),"=r"(a6),"=r"(a7)
                 : "l"(p));
    f8 r;
    r.v[0]=__uint_as_float(a0); r.v[1]=__uint_as_float(a1);
    r.v[2]=__uint_as_float(a2); r.v[3]=__uint_as_float(a3);
    r.v[4]=__uint_as_float(a4); r.v[5]=__uint_as_float(a5);
    r.v[6]=__uint_as_float(a6); r.v[7]=__uint_as_float(a7);
    return r;
}
__device__ __forceinline__ f8 ld8_stream(const float* p) {
    unsigned a0,a1,a2,a3,a4,a5,a6,a7;
    asm volatile("ld.global.nc.L2::evict_first.v8.b32 {%0,%1,%2,%3,%4,%5,%6,%7}, [%8];"
                 : "=r"(a0),"=r"(a1),"=r"(a2),"=r"(a3),
                   "=r"(a4),"=r"(a5),"=r"(a6),"=r"(a7)
                 : "l"(p));
    f8 r;
    r.v[0]=__uint_as_float(a0); r.v[1]=__uint_as_float(a1);
    r.v[2]=__uint_as_float(a2); r.v[3]=__uint_as_float(a3);
    r.v[4]=__uint_as_float(a4); r.v[5]=__uint_as_float(a5);
    r.v[6]=__uint_as_float(a6); r.v[7]=__uint_as_float(a7);
    return r;
}
__device__ __forceinline__ float m8(const f8& x) {
    float a = fmaxf(fabsf(x.v[0]), fabsf(x.v[1]));
    float b = fmaxf(fabsf(x.v[2]), fabsf(x.v[3]));
    float c = fmaxf(fabsf(x.v[4]), fabsf(x.v[5]));
    float d = fmaxf(fabsf(x.v[6]), fabsf(x.v[7]));
    return fmaxf(fmaxf(a, b), fmaxf(c, d));
}

__global__ __launch_bounds__(BDIM, 2)
void fused_loss_kernel(const float* __restrict__ pred,
                       const float* __restrict__ lab,
                       float* __restrict__ out,
                       int B)
{
    const int b = blockIdx.x;
    const size_t row = (size_t)b * NCOL;
    const float* Lr = lab  + row;
    const float* Lj = Lr + HALF;
    const float* Pr = pred + row;
    const float* Pj = Pr + HALF;

    __shared__ int  s_min_r, s_max_r, s_min_i, s_max_i;
    __shared__ int  s_b[4];
    __shared__ bool s_is_last;
    if (threadIdx.x == 0) {
        s_min_r = INT_MAX; s_max_r = -1;
        s_min_i = INT_MAX; s_max_i = -1;
    }
    __syncthreads();

    const int lane = threadIdx.x & 31;
    const int warp = threadIdx.x >> 5;

    // ==== Phase 1: contiguous scan of 256KB label row, 8-granular bounds =====
    // Proven predicated int min/max tracking (R8/R11/R15).
    int tmin_r = INT_MAX, tmax_r = -1;
    int tmin_i = INT_MAX, tmax_i = -1;

    #pragma unroll 4
    for (int it = 0; it < NIT8; it++) {                  // real half
        int c8 = threadIdx.x + it * BDIM;
        f8 v = ld8_keep(Lr + (size_t)c8 * 8);
        if (m8(v) > THRESH) { tmin_r = min(tmin_r, c8); tmax_r = max(tmax_r, c8); }
    }
    #pragma unroll 4
    for (int it = 0; it < NIT8; it++) {                  // imag half
        int c8 = threadIdx.x + it * BDIM;
        f8 v = ld8_keep(Lj + (size_t)c8 * 8);
        if (m8(v) > THRESH) { tmin_i = min(tmin_i, c8); tmax_i = max(tmax_i, c8); }
    }

    // ==== Phase 2 IMMEDIATELY: no reduce, no barrier between phases ==========
    // (Phase 2 never reads the bounds, so nothing here needs to synchronize.)
    float accR = 0.0f, accI = 0.0f, accQ = 0.0f;

    for (int it = 0; it < NIT8; it++) {
        size_t e = (size_t)(threadIdx.x + it * BDIM) * 8;
        f8 L  = ld8_stream(Lr + e);
        f8 Li = ld8_stream(Lj + e);
        f8 P  = ld8_stream(Pr + e);
        f8 Pi = ld8_stream(Pj + e);

        #pragma unroll
        for (int k = 0; k < 8; k++) {
            float lrx = L.v[k],  lix = Li.v[k];
            float prx = P.v[k],  pix = Pi.v[k];

            float dr   = prx - lrx;
            float di   = pix - lix;
            float dint = fmaf(pix, pix, prx * prx) - fmaf(lix, lix, lrx * lrx);

            accR = fmaf(dr, dr, accR);
            accI = fmaf(di, di, accI);
            accQ = fmaf(dint, dint, accQ);
        }
    }
    float acc = accR + accI + 50.0f * accQ;

    // ==== Bounds reduction + refinement (off the streaming path) =============
    #pragma unroll
    for (int off = 16; off > 0; off >>= 1) {
        tmin_r = min(tmin_r, __shfl_xor_sync(0xFFFFFFFFu, tmin_r, off));
        tmax_r = max(tmax_r, __shfl_xor_sync(0xFFFFFFFFu, tmax_r, off));
        tmin_i = min(tmin_i, __shfl_xor_sync(0xFFFFFFFFu, tmin_i, off));
        tmax_i = max(tmax_i, __shfl_xor_sync(0xFFFFFFFFu, tmax_i, off));
    }
    if (lane == 0) {
        atomicMin(&s_min_r, tmin_r);
        atomicMax(&s_max_r, tmax_r);
        atomicMin(&s_min_i, tmin_i);
        atomicMax(&s_max_i, tmax_i);
    }
    __syncthreads();

    // refine 8-granular bounds to element-exact (cache hits, <=7 steps each)
    if (threadIdx.x == 0) {
        int fr = 0, lrr = HALF - 1, fi = 0, lii = HALF - 1;
        if (s_max_r >= 0) {
            int f = s_min_r * 8;     while (fabsf(Lr[f]) <= THRESH) f++;
            int l = s_max_r * 8 + 7; while (fabsf(Lr[l]) <= THRESH) l--;
            fr = f; lrr = l;
        }
        if (s_max_i >= 0) {
            int f = s_min_i * 8;     while (fabsf(Lj[f]) <= THRESH) f++;
            int l = s_max_i * 8 + 7; while (fabsf(Lj[l]) <= THRESH) l--;
            fi = f; lii = l;
        }
        s_b[0] = fr; s_b[1] = lrr; s_b[2] = fi; s_b[3] = lii;
    }
    __syncthreads();

    // ==== Correction: (P-1) * sum of d^2 outside [first,last] (tiny) =========
    {
        const int fr = s_b[0], lrr = s_b[1], fi = s_b[2], lii = s_b[3];
        float corr = 0.0f;
        for (int j = threadIdx.x; j < fr; j += BDIM)             { float d = Pr[j] - Lr[j]; corr = fmaf(d, d, corr); }
        for (int j = lrr + 1 + threadIdx.x; j < HALF; j += BDIM) { float d = Pr[j] - Lr[j]; corr = fmaf(d, d, corr); }
        for (int j = threadIdx.x; j < fi; j += BDIM)             { float d = Pj[j] - Lj[j]; corr = fmaf(d, d, corr); }
        for (int j = lii + 1 + threadIdx.x; j < HALF; j += BDIM) { float d = Pj[j] - Lj[j]; corr = fmaf(d, d, corr); }
        acc = fmaf(PENALTY - 1.0f, corr, acc);
    }

    // ---- block sum reduction -------------------------------------------------
    __shared__ float s_warp[BDIM / 32];
    #pragma unroll
    for (int off = 16; off > 0; off >>= 1)
        acc += __shfl_xor_sync(0xFFFFFFFFu, acc, off);
    if (lane == 0)
        s_warp[warp] = acc;
    __syncthreads();
    if (threadIdx.x < 32) {
        float v = (threadIdx.x < BDIM / 32) ? s_warp[threadIdx.x] : 0.0f;
        #pragma unroll
        for (int off = 16; off > 0; off >>= 1)
            v += __shfl_xor_sync(0xFFFFFFFFu, v, off);
        if (threadIdx.x == 0)
            g_partials[b] = v;
    }

    // ---- last CTA folds the per-row partials (self-resetting for graphs) ----
    if (threadIdx.x == 0) {
        __threadfence();
        unsigned int ticket = atomicAdd(&g_counter, 1u);
        s_is_last = (ticket == (unsigned int)(B - 1));
    }
    __syncthreads();

    if (s_is_last) {
        __threadfence();
        __shared__ float s_fin[256];
        if (threadIdx.x < 256)
            s_fin[threadIdx.x] = (threadIdx.x < B) ? g_partials[threadIdx.x] : 0.0f;
        __syncthreads();
        #pragma unroll
        for (int st = 128; st > 0; st >>= 1) {
            if (threadIdx.x < st) s_fin[threadIdx.x] += s_fin[threadIdx.x + st];
            __syncthreads();
        }
        if (threadIdx.x == 0) {
            out[0] = s_fin[0] / ((float)HALF * (float)B);
            g_counter = 0;   // reset for graph replay
        }
    }
}

extern "C" void kernel_launch(void* const* d_in, const int* in_sizes, int n_in,
                              void* d_out, int out_size)
{
    const float* pred = (const float*)d_in[0];
    const float* lab  = (const float*)d_in[1];
    float* out = (float*)d_out;

    const int B = in_sizes[0] / NCOL;   // 256

    fused_loss_kernel<<<B, BDIM>>>(pred, lab, out, B);
}